// round 13
// baseline (speedup 1.0000x reference)
#include <cuda_runtime.h>

typedef unsigned long long ull;

#define DIM 16

// ---------- packed f32x2 helpers ----------
__device__ __forceinline__ ull pk2(float lo, float hi) {
    ull r; asm("mov.b64 %0, {%1, %2};" : "=l"(r) : "f"(lo), "f"(hi)); return r;
}
__device__ __forceinline__ void upk2(ull v, float& lo, float& hi) {
    asm("mov.b64 {%0, %1}, %2;" : "=f"(lo), "=f"(hi) : "l"(v));
}
__device__ __forceinline__ ull f2mul(ull a, ull b) {
    ull r; asm("mul.rn.f32x2 %0, %1, %2;" : "=l"(r) : "l"(a), "l"(b)); return r;
}
__device__ __forceinline__ ull f2add(ull a, ull b) {
    ull r; asm("add.rn.f32x2 %0, %1, %2;" : "=l"(r) : "l"(a), "l"(b)); return r;
}
__device__ __forceinline__ ull f2fma(ull a, ull b, ull c) {
    ull r; asm("fma.rn.f32x2 %0, %1, %2, %3;" : "=l"(r) : "l"(a), "l"(b), "l"(c)); return r;
}
#define NEG1_PK 0xBF800000BF800000ULL   // (-1, -1)
#define NEG2_PK 0xC0000000C0000000ULL   // (-2, -2)
#define HALF_PK 0x3F0000003F000000ULL   // (0.5, 0.5)
__device__ __forceinline__ ull f2sub(ull a, ull b) { return f2fma(NEG1_PK, b, a); }

// Ring-CNOT permutation: new_state[i] = state[PERM[i]] (free register rename).
__device__ __forceinline__ void apply_perm(ull st[DIM]) {
    const int PERM[DIM] = {0, 13, 3, 14, 6, 11, 5, 8, 12, 1, 15, 2, 10, 7, 9, 4};
    ull tmp[DIM];
#pragma unroll
    for (int i = 0; i < DIM; i++) tmp[i] = st[PERM[i]];
#pragma unroll
    for (int i = 0; i < DIM; i++) st[i] = tmp[i];
}

// Tangent-shear RY on bit (cos scale deferred): u' = u - t*v ; v' = t*u + v
__device__ __forceinline__ void apply_ry_shear(ull st[DIM], int bit, float t) {
    const ull T2  = pk2(t, t);
    const ull NT2 = pk2(-t, -t);
    const int stride = 1 << bit;
#pragma unroll
    for (int i = 0; i < DIM; i++) {
        if (i & stride) continue;
        ull u = st[i];
        ull v = st[i + stride];
        st[i]          = f2fma(NT2, v, u);
        st[i + stride] = f2fma(T2, u, v);
    }
}

__global__ void __launch_bounds__(128, 11)
qlayer_kernel(const float4* __restrict__ x, const float* __restrict__ w,
              float4* __restrict__ out, int B2) {
    // ---- per-warp weight prep (no barriers, no smem, no prep kernel) ----
    int lane = threadIdx.x & 31;
    float wk = w[4 + (lane & 7)];           // uniform cacheline, L1 broadcast
    float s, c;
    __sincosf(0.5f * wk, &s, &c);           // |arg| ~ 0.02 -> fast path accurate
    float tmine = __fdividef(s, c);         // tan(w/2)

    // product of the 8 cosines (lanes 0-7 form an xor-group under {1,2,4})
    float cp = c;
    cp *= __shfl_xor_sync(0xFFFFFFFFu, cp, 1);
    cp *= __shfl_xor_sync(0xFFFFFFFFu, cp, 2);
    cp *= __shfl_xor_sync(0xFFFFFFFFu, cp, 4);
    float sc = __shfl_sync(0xFFFFFFFFu, cp, 0);   // prod over lanes 0-7
    ull scp = pk2(sc, sc);                        // folded into C0/S0 below

    float tw[8];
#pragma unroll
    for (int r = 0; r < 8; r++) tw[r] = __shfl_sync(0xFFFFFFFFu, tmine, r);

    // layer-0 weights, fused into input angles (packed half-angles)
    float4 w03 = *(const float4*)w;
    ull hp[4] = {pk2(0.5f * w03.x, 0.5f * w03.x), pk2(0.5f * w03.y, 0.5f * w03.y),
                 pk2(0.5f * w03.z, 0.5f * w03.z), pk2(0.5f * w03.w, 0.5f * w03.w)};

    int t = blockIdx.x * blockDim.x + threadIdx.x;
    if (t >= B2) return;                    // after all warp-collective shfls

    float4 xa = x[2 * t];
    float4 xb = x[2 * t + 1];

    // Fused layer-0 angles (packed): theta/2 = 0.5*x + 0.5*w0, then fast sincos.
    ull th[4];
    th[0] = f2fma(HALF_PK, pk2(xa.x, xb.x), hp[0]);
    th[1] = f2fma(HALF_PK, pk2(xa.y, xb.y), hp[1]);
    th[2] = f2fma(HALF_PK, pk2(xa.z, xb.z), hp[2]);
    th[3] = f2fma(HALF_PK, pk2(xa.w, xb.w), hp[3]);

    ull C[4], S[4];
#pragma unroll
    for (int q = 0; q < 4; q++) {
        float ta, tb, caq, saq, cbq, sbq;
        upk2(th[q], ta, tb);
        __sincosf(ta, &saq, &caq);
        __sincosf(tb, &sbq, &cbq);
        C[q] = pk2(caq, cbq);
        S[q] = pk2(saq, sbq);
    }

    // Fold the deferred cos-product scale into qubit-0 factors:
    // state scales by sc -> probabilities by sc^2 (exactly the output scale).
    C[0] = f2mul(C[0], scp);
    S[0] = f2mul(S[0], scp);

    // Tensor-product factors (bit layout: qubit q <-> bit 3-q).
    ull A0 = f2mul(C[0], C[1]), A1 = f2mul(C[0], S[1]);
    ull A2 = f2mul(S[0], C[1]), A3 = f2mul(S[0], S[1]);
    ull B0 = f2mul(C[2], C[3]), B1 = f2mul(C[2], S[3]);
    ull B2v = f2mul(S[2], C[3]), B3 = f2mul(S[2], S[3]);

    // Fused: layer-0 perm + layer-1 qubit-0 shear applied on the A factor.
    ull T0  = pk2(tw[0], tw[0]);
    ull NT0 = pk2(-tw[0], -tw[0]);
    ull A0m = f2fma(NT0, A3, A0);   // A0 - t*A3
    ull A3p = f2fma(T0,  A0, A3);   // A3 + t*A0
    ull A3m = f2fma(NT0, A0, A3);   // A3 - t*A0
    ull A0p = f2fma(T0,  A3, A0);   // A0 + t*A3
    ull A1m = f2fma(NT0, A2, A1);
    ull A2p = f2fma(T0,  A1, A2);
    ull A2m = f2fma(NT0, A1, A2);
    ull A1p = f2fma(T0,  A2, A1);

    ull st[DIM];
    st[0]  = f2mul(A0m, B0);  st[1]  = f2mul(A3m, B1);
    st[2]  = f2mul(A0m, B3);  st[3]  = f2mul(A3m, B2v);
    st[4]  = f2mul(A1m, B2v); st[5]  = f2mul(A2m, B3);
    st[6]  = f2mul(A1m, B1);  st[7]  = f2mul(A2m, B0);
    st[8]  = f2mul(A3p, B0);  st[9]  = f2mul(A0p, B1);
    st[10] = f2mul(A3p, B3);  st[11] = f2mul(A0p, B2v);
    st[12] = f2mul(A2p, B2v); st[13] = f2mul(A1p, B3);
    st[14] = f2mul(A2p, B1);  st[15] = f2mul(A1p, B0);

    // Rest of layer 1: shears on qubits 1,2,3 (bits 2,1,0), then perm.
    apply_ry_shear(st, 2, tw[1]);
    apply_ry_shear(st, 1, tw[2]);
    apply_ry_shear(st, 0, tw[3]);
    apply_perm(st);

    // Layer 2: full 4 shears + perm.
    apply_ry_shear(st, 3, tw[4]);
    apply_ry_shear(st, 2, tw[5]);
    apply_ry_shear(st, 1, tw[6]);
    apply_ry_shear(st, 0, tw[7]);
    apply_perm(st);

    // Probabilities (already carry sc^2 via folded scale).
    ull p[DIM];
#pragma unroll
    for (int i = 0; i < DIM; i++) p[i] = f2mul(st[i], st[i]);

    // Compressed expectation tree:
    //   ex = s8a - s8b           ey = e1 - e2
    //   ez = tot - 2*odd(s2)     ew = tot - 2*odd(p)
    ull s2v[8];
#pragma unroll
    for (int k = 0; k < 8; k++) s2v[k] = f2add(p[2 * k], p[2 * k + 1]);
    ull s4v[4];
#pragma unroll
    for (int k = 0; k < 4; k++) s4v[k] = f2add(s2v[2 * k], s2v[2 * k + 1]);

    ull s8a = f2add(s4v[0], s4v[1]);
    ull s8b = f2add(s4v[2], s4v[3]);
    ull tot = f2add(s8a, s8b);
    ull ex  = f2sub(s8a, s8b);                                        // qubit 0

    ull e1 = f2add(s4v[0], s4v[2]);
    ull e2 = f2add(s4v[1], s4v[3]);
    ull ey = f2sub(e1, e2);                                           // qubit 1

    ull odds2 = f2add(f2add(s2v[1], s2v[3]), f2add(s2v[5], s2v[7]));
    ull ez = f2fma(NEG2_PK, odds2, tot);                              // qubit 2

    ull oddp = f2add(f2add(f2add(p[1], p[3]),  f2add(p[5], p[7])),
                     f2add(f2add(p[9], p[11]), f2add(p[13], p[15])));
    ull ew = f2fma(NEG2_PK, oddp, tot);                               // qubit 3

    float exl, exh, eyl, eyh, ezl, ezh, ewl, ewh;
    upk2(ex, exl, exh);
    upk2(ey, eyl, eyh);
    upk2(ez, ezl, ezh);
    upk2(ew, ewl, ewh);

    out[2 * t]     = make_float4(exl, eyl, ezl, ewl);
    out[2 * t + 1] = make_float4(exh, eyh, ezh, ewh);
}

extern "C" void kernel_launch(void* const* d_in, const int* in_sizes, int n_in,
                              void* d_out, int out_size) {
    const float* x = (const float*)d_in[0];
    const float* w = (const float*)d_in[1];
    int nx = in_sizes[0];
    // Robustness to metadata ordering: weights vector has 12 elements.
    if (n_in >= 2 && in_sizes[0] == 12) {
        x = (const float*)d_in[1];
        w = (const float*)d_in[0];
        nx = in_sizes[1];
    }
    int B  = nx / 4;
    int B2 = B / 2;  // two batch elements per thread (B = 2^20)

    qlayer_kernel<<<(B2 + 127) / 128, 128>>>((const float4*)x, w, (float4*)d_out, B2);
}

// round 15
// speedup vs baseline: 1.3183x; 1.3183x over previous
#include <cuda_runtime.h>

typedef unsigned long long ull;

#define DIM 16

// ---------- packed f32x2 helpers ----------
__device__ __forceinline__ ull pk2(float lo, float hi) {
    ull r; asm("mov.b64 %0, {%1, %2};" : "=l"(r) : "f"(lo), "f"(hi)); return r;
}
__device__ __forceinline__ void upk2(ull v, float& lo, float& hi) {
    asm("mov.b64 {%0, %1}, %2;" : "=f"(lo), "=f"(hi) : "l"(v));
}
__device__ __forceinline__ ull f2mul(ull a, ull b) {
    ull r; asm("mul.rn.f32x2 %0, %1, %2;" : "=l"(r) : "l"(a), "l"(b)); return r;
}
__device__ __forceinline__ ull f2add(ull a, ull b) {
    ull r; asm("add.rn.f32x2 %0, %1, %2;" : "=l"(r) : "l"(a), "l"(b)); return r;
}
__device__ __forceinline__ ull f2fma(ull a, ull b, ull c) {
    ull r; asm("fma.rn.f32x2 %0, %1, %2, %3;" : "=l"(r) : "l"(a), "l"(b), "l"(c)); return r;
}
#define NEG1_PK 0xBF800000BF800000ULL   // (-1, -1)
#define NEG2_PK 0xC0000000C0000000ULL   // (-2, -2)
__device__ __forceinline__ ull f2sub(ull a, ull b) { return f2fma(NEG1_PK, b, a); }

// Ring-CNOT permutation: new_state[i] = state[PERM[i]] (free register rename).
__device__ __forceinline__ void apply_perm(ull st[DIM]) {
    const int PERM[DIM] = {0, 13, 3, 14, 6, 11, 5, 8, 12, 1, 15, 2, 10, 7, 9, 4};
    ull tmp[DIM];
#pragma unroll
    for (int i = 0; i < DIM; i++) tmp[i] = st[PERM[i]];
#pragma unroll
    for (int i = 0; i < DIM; i++) st[i] = tmp[i];
}

// Tangent-shear RY on bit (cos scale deferred): u' = u - t*v ; v' = t*u + v
__device__ __forceinline__ void apply_ry_shear(ull st[DIM], int bit, float t) {
    const ull T2  = pk2(t, t);
    const ull NT2 = pk2(-t, -t);
    const int stride = 1 << bit;
#pragma unroll
    for (int i = 0; i < DIM; i++) {
        if (i & stride) continue;
        ull u = st[i];
        ull v = st[i + stride];
        st[i]          = f2fma(NT2, v, u);
        st[i + stride] = f2fma(T2, u, v);
    }
}

__global__ void __launch_bounds__(128, 10)
qlayer_kernel(const float4* __restrict__ x, const float* __restrict__ w,
              float4* __restrict__ out, int B2) {
    // ---- per-warp weight prep (no barriers, no smem, no prep kernel) ----
    int lane = threadIdx.x & 31;
    float wk = w[4 + (lane & 7)];           // uniform cacheline, L1 broadcast
    float s, c;
    __sincosf(0.5f * wk, &s, &c);           // |arg| ~ 0.02 -> fast path accurate
    float tmine = __fdividef(s, c);         // tan(w/2)

    // product of the 8 cosines (lanes 0-7 form an xor-group under {1,2,4})
    float cp = c;
    cp *= __shfl_xor_sync(0xFFFFFFFFu, cp, 1);
    cp *= __shfl_xor_sync(0xFFFFFFFFu, cp, 2);
    cp *= __shfl_xor_sync(0xFFFFFFFFu, cp, 4);
    float sc = __shfl_sync(0xFFFFFFFFu, cp, 0);   // prod over lanes 0-7
    ull sc2 = pk2(sc * sc, sc * sc);

    float tw[8];
#pragma unroll
    for (int r = 0; r < 8; r++) tw[r] = __shfl_sync(0xFFFFFFFFu, tmine, r);

    // layer-0 weights, fused into input angles
    float4 w03 = *(const float4*)w;
    float h0 = 0.5f * w03.x, h1 = 0.5f * w03.y, h2 = 0.5f * w03.z, h3 = 0.5f * w03.w;

    int t = blockIdx.x * blockDim.x + threadIdx.x;
    if (t >= B2) return;                    // after all warp-collective shfls

    float4 xa = x[2 * t];
    float4 xb = x[2 * t + 1];

    // Fused layer-0 angles: theta_q/2 = 0.5*x_q + 0.5*w_0q, fast sincos.
    float ca[4], sa[4], cb[4], sb[4];
    __sincosf(fmaf(0.5f, xa.x, h0), &sa[0], &ca[0]);
    __sincosf(fmaf(0.5f, xa.y, h1), &sa[1], &ca[1]);
    __sincosf(fmaf(0.5f, xa.z, h2), &sa[2], &ca[2]);
    __sincosf(fmaf(0.5f, xa.w, h3), &sa[3], &ca[3]);
    __sincosf(fmaf(0.5f, xb.x, h0), &sb[0], &cb[0]);
    __sincosf(fmaf(0.5f, xb.y, h1), &sb[1], &cb[1]);
    __sincosf(fmaf(0.5f, xb.z, h2), &sb[2], &cb[2]);
    __sincosf(fmaf(0.5f, xb.w, h3), &sb[3], &cb[3]);

    ull C[4], S[4];
#pragma unroll
    for (int q = 0; q < 4; q++) {
        C[q] = pk2(ca[q], cb[q]);
        S[q] = pk2(sa[q], sb[q]);
    }

    // Tensor-product factors (bit layout: qubit q <-> bit 3-q).
    ull A0 = f2mul(C[0], C[1]), A1 = f2mul(C[0], S[1]);
    ull A2 = f2mul(S[0], C[1]), A3 = f2mul(S[0], S[1]);
    ull B0 = f2mul(C[2], C[3]), B1 = f2mul(C[2], S[3]);
    ull B2v = f2mul(S[2], C[3]), B3 = f2mul(S[2], S[3]);

    // Fused: layer-0 perm + layer-1 qubit-0 shear applied on the A factor.
    ull T0  = pk2(tw[0], tw[0]);
    ull NT0 = pk2(-tw[0], -tw[0]);
    ull A0m = f2fma(NT0, A3, A0);   // A0 - t*A3
    ull A3p = f2fma(T0,  A0, A3);   // A3 + t*A0
    ull A3m = f2fma(NT0, A0, A3);   // A3 - t*A0
    ull A0p = f2fma(T0,  A3, A0);   // A0 + t*A3
    ull A1m = f2fma(NT0, A2, A1);
    ull A2p = f2fma(T0,  A1, A2);
    ull A2m = f2fma(NT0, A1, A2);
    ull A1p = f2fma(T0,  A2, A1);

    ull st[DIM];
    st[0]  = f2mul(A0m, B0);  st[1]  = f2mul(A3m, B1);
    st[2]  = f2mul(A0m, B3);  st[3]  = f2mul(A3m, B2v);
    st[4]  = f2mul(A1m, B2v); st[5]  = f2mul(A2m, B3);
    st[6]  = f2mul(A1m, B1);  st[7]  = f2mul(A2m, B0);
    st[8]  = f2mul(A3p, B0);  st[9]  = f2mul(A0p, B1);
    st[10] = f2mul(A3p, B3);  st[11] = f2mul(A0p, B2v);
    st[12] = f2mul(A2p, B2v); st[13] = f2mul(A1p, B3);
    st[14] = f2mul(A2p, B1);  st[15] = f2mul(A1p, B0);

    // Rest of layer 1: shears on qubits 1,2,3 (bits 2,1,0), then perm.
    apply_ry_shear(st, 2, tw[1]);
    apply_ry_shear(st, 1, tw[2]);
    apply_ry_shear(st, 0, tw[3]);
    apply_perm(st);

    // Layer 2: full 4 shears + perm.
    apply_ry_shear(st, 3, tw[4]);
    apply_ry_shear(st, 2, tw[5]);
    apply_ry_shear(st, 1, tw[6]);
    apply_ry_shear(st, 0, tw[7]);
    apply_perm(st);

    // Probabilities + compressed expectation tree:
    //   ex = s8a - s8b            ey = (s4_0+s4_2) - (s4_1+s4_3)
    //   ez = tot - 2*odd(s2)      ew = tot - 2*odd(p)
    ull p[DIM];
#pragma unroll
    for (int i = 0; i < DIM; i++) p[i] = f2mul(st[i], st[i]);

    ull s2v[8];
#pragma unroll
    for (int k = 0; k < 8; k++) s2v[k] = f2add(p[2 * k], p[2 * k + 1]);
    ull s4v[4];
#pragma unroll
    for (int k = 0; k < 4; k++) s4v[k] = f2add(s2v[2 * k], s2v[2 * k + 1]);

    ull s8a = f2add(s4v[0], s4v[1]);
    ull s8b = f2add(s4v[2], s4v[3]);
    ull tot = f2add(s8a, s8b);

    ull ex = f2mul(sc2, f2sub(s8a, s8b));                                 // qubit 0
    ull ey = f2mul(sc2, f2sub(f2add(s4v[0], s4v[2]), f2add(s4v[1], s4v[3]))); // qubit 1

    ull odds2 = f2add(f2add(s2v[1], s2v[3]), f2add(s2v[5], s2v[7]));
    ull ez = f2mul(sc2, f2fma(NEG2_PK, odds2, tot));                      // qubit 2

    ull oddp = f2add(f2add(f2add(p[1], p[3]),  f2add(p[5], p[7])),
                     f2add(f2add(p[9], p[11]), f2add(p[13], p[15])));
    ull ew = f2mul(sc2, f2fma(NEG2_PK, oddp, tot));                       // qubit 3

    float exl, exh, eyl, eyh, ezl, ezh, ewl, ewh;
    upk2(ex, exl, exh);
    upk2(ey, eyl, eyh);
    upk2(ez, ezl, ezh);
    upk2(ew, ewl, ewh);

    out[2 * t]     = make_float4(exl, eyl, ezl, ewl);
    out[2 * t + 1] = make_float4(exh, eyh, ezh, ewh);
}

extern "C" void kernel_launch(void* const* d_in, const int* in_sizes, int n_in,
                              void* d_out, int out_size) {
    const float* x = (const float*)d_in[0];
    const float* w = (const float*)d_in[1];
    int nx = in_sizes[0];
    // Robustness to metadata ordering: weights vector has 12 elements.
    if (n_in >= 2 && in_sizes[0] == 12) {
        x = (const float*)d_in[1];
        w = (const float*)d_in[0];
        nx = in_sizes[1];
    }
    int B  = nx / 4;
    int B2 = B / 2;  // two batch elements per thread (B = 2^20)

    qlayer_kernel<<<(B2 + 127) / 128, 128>>>((const float4*)x, w, (float4*)d_out, B2);
}